// round 6
// baseline (speedup 1.0000x reference)
#include <cuda_runtime.h>

#define N_NODES 50000
#define N_EDGES 800000
#define D_IN 64
#define D_OUT 64
#define E_DIM 32
#define NK 96          // D_IN + E_DIM
#define BN_EPS 1e-5f
#define NGROUPS ((N_NODES + 31) / 32)   // 1563

// ---------------- scratch (static device memory) ----------------
__device__ __align__(16) float g_aggX[N_NODES * D_IN];
__device__ __align__(16) float g_aggE[N_NODES * E_DIM];
__device__ __align__(16) float g_h[N_NODES * D_OUT];
__device__ int g_cnt[N_NODES];
__device__ int g_locpre[65536];
__device__ int g_part[256];
__device__ int g_partoff[256];
__device__ int g_rowstart[N_NODES + 1];
__device__ int g_cursor[N_NODES];
__device__ int g_esrc[N_EDGES];
__device__ int g_eid[N_EDGES];
__device__ __align__(16) float g_sum[D_OUT];
__device__ __align__(16) float g_sumsq[D_OUT];
__device__ __align__(8) float2 g_Wp[NK * 32];     // k<64: W1 pairs; k>=64: C1=We@W1 pairs
__device__ __align__(8) float2 g_W2p[D_OUT * 32];
__device__ __align__(8) float2 g_c2p[32];         // (be@W1)[d], [d+32]
__device__ __align__(8) float2 g_b1p[32];
__device__ __align__(8) float2 g_b2p[32];
__device__ __align__(16) float g_scalef[D_OUT];
__device__ __align__(16) float g_shiftf[D_OUT];

// ---------------- zero ----------------
__global__ void zero_kernel() {
    int idx = blockIdx.x * blockDim.x + threadIdx.x;
    if (idx < N_NODES) g_cnt[idx] = 0;
    if (idx < D_OUT) { g_sum[idx] = 0.f; g_sumsq[idx] = 0.f; }
}

// ---------------- prep: pack weights, compute C1 = We@W1, c2 = be@W1 ----------
__global__ void prep_kernel(const float* __restrict__ We,
                            const float* __restrict__ be,
                            const float* __restrict__ W1,
                            const float* __restrict__ b1,
                            const float* __restrict__ W2,
                            const float* __restrict__ b2) {
    __shared__ float W1s[D_IN * D_OUT];
    int tid = threadIdx.x;
    for (int i = tid; i < D_IN * D_OUT; i += 256) W1s[i] = W1[i];
    __syncthreads();
    // W1 pairs
    for (int i = tid; i < 64 * 32; i += 256) {
        int k = i >> 5, l = i & 31;
        g_Wp[i] = make_float2(W1s[k * 64 + l], W1s[k * 64 + l + 32]);
    }
    // C1 rows (E_DIM x 64), packed as pairs
    for (int i = tid; i < E_DIM * 32; i += 256) {
        int kk = i >> 5, l = i & 31;
        float sa = 0.f, sb = 0.f;
        #pragma unroll 8
        for (int m = 0; m < 64; m++) {
            float w = We[kk * 64 + m];
            sa += w * W1s[m * 64 + l];
            sb += w * W1s[m * 64 + l + 32];
        }
        g_Wp[(64 + kk) * 32 + l] = make_float2(sa, sb);
    }
    // W2 pairs
    for (int i = tid; i < 64 * 32; i += 256) {
        int k = i >> 5, l = i & 31;
        g_W2p[i] = make_float2(W2[k * 64 + l], W2[k * 64 + l + 32]);
    }
    if (tid < 32) {
        float sa = 0.f, sb = 0.f;
        #pragma unroll 8
        for (int m = 0; m < 64; m++) {
            float w = be[m];
            sa += w * W1s[m * 64 + tid];
            sb += w * W1s[m * 64 + tid + 32];
        }
        g_c2p[tid] = make_float2(sa, sb);
        g_b1p[tid] = make_float2(b1[tid], b1[tid + 32]);
        g_b2p[tid] = make_float2(b2[tid], b2[tid + 32]);
    }
}

// ---------------- CSR build ----------------
__global__ void hist_kernel(const int* __restrict__ ei) {
    int e = blockIdx.x * blockDim.x + threadIdx.x;
    if (e < N_EDGES) atomicAdd(&g_cnt[ei[N_EDGES + e]], 1);
}

__global__ void scan1_kernel() {   // 256 blocks x 256
    __shared__ int sd[256];
    int t = threadIdx.x;
    int g = blockIdx.x * 256 + t;
    int v = (g < N_NODES) ? g_cnt[g] : 0;
    sd[t] = v;
    __syncthreads();
    #pragma unroll
    for (int off = 1; off < 256; off <<= 1) {
        int y = (t >= off) ? sd[t - off] : 0;
        __syncthreads();
        sd[t] += y;
        __syncthreads();
    }
    g_locpre[g] = sd[t] - v;           // exclusive within block
    if (t == 255) g_part[blockIdx.x] = sd[255];
}

__global__ void scan2_kernel() {   // 1 block x 256
    __shared__ int sd[256];
    int t = threadIdx.x;
    int v = g_part[t];
    sd[t] = v;
    __syncthreads();
    #pragma unroll
    for (int off = 1; off < 256; off <<= 1) {
        int y = (t >= off) ? sd[t - off] : 0;
        __syncthreads();
        sd[t] += y;
        __syncthreads();
    }
    g_partoff[t] = sd[t] - v;
}

__global__ void scan3_kernel() {   // 256 blocks x 256
    int t = threadIdx.x;
    int g = blockIdx.x * 256 + t;
    if (g < N_NODES) {
        int rs = g_locpre[g] + g_partoff[blockIdx.x];
        g_rowstart[g] = rs;
        g_cursor[g] = rs;
    }
    if (g == 0) g_rowstart[N_NODES] = N_EDGES;
}

__global__ void scatter_kernel(const int* __restrict__ ei) {
    int e = blockIdx.x * blockDim.x + threadIdx.x;
    if (e >= N_EDGES) return;
    int dst = ei[N_EDGES + e];
    int pos = atomicAdd(&g_cursor[dst], 1);
    g_esrc[pos] = ei[e];
    g_eid[pos] = e;
}

// ---------------- gather: one warp per node, no atomics ----------------
__global__ void gather_kernel(const float4* __restrict__ x4,
                              const float2* __restrict__ ea2) {
    int gw = (blockIdx.x * blockDim.x + threadIdx.x) >> 5;
    if (gw >= N_NODES) return;
    int lane = threadIdx.x & 31;
    int start = g_rowstart[gw], end = g_rowstart[gw + 1];
    float4 aX = make_float4(0.f, 0.f, 0.f, 0.f);
    float2 aE = make_float2(0.f, 0.f);
    bool isX = lane < 16;
    int li = lane & 15;
    int p = start;
    for (; p + 2 <= end; p += 2) {
        int s0 = g_esrc[p], s1 = g_esrc[p + 1];
        int e0 = g_eid[p], e1 = g_eid[p + 1];
        if (isX) {
            float4 v0 = __ldg(&x4[(size_t)s0 * 16 + li]);
            float4 v1 = __ldg(&x4[(size_t)s1 * 16 + li]);
            aX.x += v0.x + v1.x; aX.y += v0.y + v1.y;
            aX.z += v0.z + v1.z; aX.w += v0.w + v1.w;
        } else {
            float2 v0 = __ldg(&ea2[(size_t)e0 * 16 + li]);
            float2 v1 = __ldg(&ea2[(size_t)e1 * 16 + li]);
            aE.x += v0.x + v1.x; aE.y += v0.y + v1.y;
        }
    }
    if (p < end) {
        int s0 = g_esrc[p];
        int e0 = g_eid[p];
        if (isX) {
            float4 v0 = __ldg(&x4[(size_t)s0 * 16 + li]);
            aX.x += v0.x; aX.y += v0.y; aX.z += v0.z; aX.w += v0.w;
        } else {
            float2 v0 = __ldg(&ea2[(size_t)e0 * 16 + li]);
            aE.x += v0.x; aE.y += v0.y;
        }
    }
    if (isX) ((float4*)g_aggX)[gw * 16 + li] = aX;
    else     ((float2*)g_aggE)[gw * 16 + li] = aE;
}

// ---------------- node_h: h = (aggX+x)@W1 + aggE@C1 + deg*c2 + b1 ; stats ------
// 8 warps/block, 4 rows/warp. Activations staged transposed (stT[k] = float4
// over 4 rows) -> inner loop is 1 LDS.128 + 1 LDS.64 + 8 FFMA per k.
__global__ __launch_bounds__(256) void node_h_kernel(const float* __restrict__ x) {
    __shared__ __align__(8) float2 Wp[NK * 32];      // 24KB
    __shared__ __align__(16) float stT[8][NK * 4];   // 12KB
    __shared__ float2 c2s[32], b1s[32];
    __shared__ float bsum[64], bsq[64];

    int tid = threadIdx.x;
    for (int i = tid; i < NK * 32; i += 256) Wp[i] = g_Wp[i];
    if (tid < 32) { c2s[tid] = g_c2p[tid]; b1s[tid] = g_b1p[tid]; }
    if (tid < 64) { bsum[tid] = 0.f; bsq[tid] = 0.f; }
    __syncthreads();

    int warp = tid >> 5, lane = tid & 31;
    float2 c2v = c2s[lane], b1v = b1s[lane];
    float s0 = 0.f, q0 = 0.f, s1 = 0.f, q1 = 0.f;

    for (int g = blockIdx.x; g < NGROUPS; g += gridDim.x) {
        int rowBase = g * 32 + warp * 4;
        // stage 4 rows x 96 floats, transposed
        #pragma unroll
        for (int j = 0; j < 3; j++) {
            int task = j * 32 + lane;           // 0..95
            int r = task / 24, c = task % 24;   // c<16: x-part chunk, else aggE
            int row = rowBase + r;
            float4 v = make_float4(0.f, 0.f, 0.f, 0.f);
            if (row < N_NODES) {
                if (c < 16) {
                    float4 a = ((const float4*)g_aggX)[row * 16 + c];
                    float4 xv = __ldg(&((const float4*)x)[row * 16 + c]);
                    v = make_float4(a.x + xv.x, a.y + xv.y, a.z + xv.z, a.w + xv.w);
                } else {
                    v = ((const float4*)g_aggE)[row * 8 + (c - 16)];
                }
            }
            int k0 = c * 4;   // covers k in [0,96): x-part k=4c (c<16); aggE k=64+(c-16)*4=4c
            stT[warp][(k0 + 0) * 4 + r] = v.x;
            stT[warp][(k0 + 1) * 4 + r] = v.y;
            stT[warp][(k0 + 2) * 4 + r] = v.z;
            stT[warp][(k0 + 3) * 4 + r] = v.w;
        }
        __syncwarp();

        float h0[4], h1[4];
        #pragma unroll
        for (int r = 0; r < 4; r++) {
            int row = rowBase + r;
            float dg = 0.f;
            if (row < N_NODES) dg = (float)(g_rowstart[row + 1] - g_rowstart[row]);
            h0[r] = dg * c2v.x + b1v.x;
            h1[r] = dg * c2v.y + b1v.y;
        }
        const float4* st4 = (const float4*)&stT[warp][0];
        #pragma unroll 8
        for (int k = 0; k < NK; k++) {
            float4 a = st4[k];
            float2 w = Wp[k * 32 + lane];
            h0[0] += a.x * w.x; h0[1] += a.y * w.x; h0[2] += a.z * w.x; h0[3] += a.w * w.x;
            h1[0] += a.x * w.y; h1[1] += a.y * w.y; h1[2] += a.z * w.y; h1[3] += a.w * w.y;
        }
        #pragma unroll
        for (int r = 0; r < 4; r++) {
            int row = rowBase + r;
            if (row < N_NODES) {
                g_h[row * 64 + lane] = h0[r];
                g_h[row * 64 + 32 + lane] = h1[r];
                s0 += h0[r]; q0 += h0[r] * h0[r];
                s1 += h1[r]; q1 += h1[r] * h1[r];
            }
        }
        __syncwarp();
    }
    atomicAdd(&bsum[lane], s0);      atomicAdd(&bsq[lane], q0);
    atomicAdd(&bsum[lane + 32], s1); atomicAdd(&bsq[lane + 32], q1);
    __syncthreads();
    if (tid < 64) { atomicAdd(&g_sum[tid], bsum[tid]); atomicAdd(&g_sumsq[tid], bsq[tid]); }
}

// ---------------- bn finalize ----------------
__global__ void bn_kernel(const float* __restrict__ gamma,
                          const float* __restrict__ beta) {
    int d = threadIdx.x;   // 64 threads
    float n = (float)N_NODES;
    float mean = g_sum[d] / n;
    float var = g_sumsq[d] / n - mean * mean;
    float rstd = rsqrtf(var + BN_EPS);
    float sc = gamma[d] * rstd;
    g_scalef[d] = sc;
    g_shiftf[d] = beta[d] - mean * sc;
}

// ---------------- node_out: out = relu(bn(h)) @ W2 + b2 ----------------
__global__ __launch_bounds__(256) void node_out_kernel(float* __restrict__ out) {
    __shared__ __align__(8) float2 W2p[64 * 32];     // 16KB
    __shared__ __align__(16) float stT[8][64 * 4];   // 8KB
    __shared__ __align__(16) float scf[64], shf[64];
    __shared__ float2 b2s[32];

    int tid = threadIdx.x;
    for (int i = tid; i < 64 * 32; i += 256) W2p[i] = g_W2p[i];
    if (tid < 64) { scf[tid] = g_scalef[tid]; shf[tid] = g_shiftf[tid]; }
    if (tid < 32) b2s[tid] = g_b2p[tid];
    __syncthreads();

    int warp = tid >> 5, lane = tid & 31;
    float2 b2v = b2s[lane];

    for (int g = blockIdx.x; g < NGROUPS; g += gridDim.x) {
        int rowBase = g * 32 + warp * 4;
        #pragma unroll
        for (int j = 0; j < 2; j++) {
            int task = j * 32 + lane;          // 0..63
            int r = task >> 4, c = task & 15;
            int row = rowBase + r;
            float4 v = make_float4(0.f, 0.f, 0.f, 0.f);
            if (row < N_NODES) {
                float4 hv = ((const float4*)g_h)[row * 16 + c];
                float4 sc = ((const float4*)scf)[c];
                float4 sh = ((const float4*)shf)[c];
                v.x = fmaxf(0.f, hv.x * sc.x + sh.x);
                v.y = fmaxf(0.f, hv.y * sc.y + sh.y);
                v.z = fmaxf(0.f, hv.z * sc.z + sh.z);
                v.w = fmaxf(0.f, hv.w * sc.w + sh.w);
            }
            int k0 = c * 4;
            stT[warp][(k0 + 0) * 4 + r] = v.x;
            stT[warp][(k0 + 1) * 4 + r] = v.y;
            stT[warp][(k0 + 2) * 4 + r] = v.z;
            stT[warp][(k0 + 3) * 4 + r] = v.w;
        }
        __syncwarp();

        float y0[4], y1[4];
        #pragma unroll
        for (int r = 0; r < 4; r++) { y0[r] = b2v.x; y1[r] = b2v.y; }
        const float4* st4 = (const float4*)&stT[warp][0];
        #pragma unroll 8
        for (int k = 0; k < 64; k++) {
            float4 a = st4[k];
            float2 w = W2p[k * 32 + lane];
            y0[0] += a.x * w.x; y0[1] += a.y * w.x; y0[2] += a.z * w.x; y0[3] += a.w * w.x;
            y1[0] += a.x * w.y; y1[1] += a.y * w.y; y1[2] += a.z * w.y; y1[3] += a.w * w.y;
        }
        #pragma unroll
        for (int r = 0; r < 4; r++) {
            int row = rowBase + r;
            if (row < N_NODES) {
                out[row * 64 + lane] = y0[r];
                out[row * 64 + 32 + lane] = y1[r];
            }
        }
        __syncwarp();
    }
}

// ---------------- launch ----------------
extern "C" void kernel_launch(void* const* d_in, const int* in_sizes, int n_in,
                              void* d_out, int out_size) {
    const float* x     = (const float*)d_in[0];
    const int* ei      = (const int*)d_in[1];
    const float* ea    = (const float*)d_in[2];
    const float* We    = (const float*)d_in[3];
    const float* be    = (const float*)d_in[4];
    const float* W1    = (const float*)d_in[5];
    const float* b1    = (const float*)d_in[6];
    const float* gamma = (const float*)d_in[7];
    const float* beta  = (const float*)d_in[8];
    const float* W2    = (const float*)d_in[9];
    const float* b2    = (const float*)d_in[10];
    float* out         = (float*)d_out;

    zero_kernel<<<(N_NODES + 255) / 256, 256>>>();
    prep_kernel<<<1, 256>>>(We, be, W1, b1, W2, b2);

    hist_kernel<<<(N_EDGES + 255) / 256, 256>>>(ei);
    scan1_kernel<<<256, 256>>>();
    scan2_kernel<<<1, 256>>>();
    scan3_kernel<<<256, 256>>>();
    scatter_kernel<<<(N_EDGES + 255) / 256, 256>>>(ei);

    gather_kernel<<<(N_NODES * 32 + 255) / 256, 256>>>((const float4*)x, (const float2*)ea);

    node_h_kernel<<<NGROUPS, 256>>>(x);
    bn_kernel<<<1, 64>>>(gamma, beta);
    node_out_kernel<<<NGROUPS, 256>>>(out);
}

// round 7
// speedup vs baseline: 1.1234x; 1.1234x over previous
#include <cuda_runtime.h>

#define N_NODES 50000
#define N_EDGES 800000
#define D_IN 64
#define D_OUT 64
#define E_DIM 32
#define NK 96          // D_IN + E_DIM
#define BN_EPS 1e-5f
#define NGROUPS ((N_NODES + 31) / 32)   // 1563

// f32x2 packed helpers (SASS FFMA2 path — PTX-only)
#define FMA2(acc, a, b) \
    asm("fma.rn.f32x2 %0, %1, %2, %3;" : "=l"(acc) : "l"(a), "l"(b), "l"(acc))
#define PACK2(out, lo, hi) \
    asm("mov.b64 %0, {%1, %2};" : "=l"(out) : "f"(lo), "f"(hi))
#define UNPACK2(lo, hi, in) \
    asm("mov.b64 {%0, %1}, %2;" : "=f"(lo), "=f"(hi) : "l"(in))

// ---------------- scratch (static device memory; 16B aligned) ----------------
__device__ __align__(16) float g_aggX[N_NODES * D_IN];
__device__ __align__(16) float g_aggE[N_NODES * E_DIM];
__device__ __align__(16) float g_deg[N_NODES];
__device__ __align__(16) float g_h[N_NODES * D_OUT];
__device__ __align__(16) float g_sum[D_OUT];
__device__ __align__(16) float g_sumsq[D_OUT];
__device__ __align__(8) float2 g_Wp[NK * 32];     // k<64: W1 (w_d, w_d+32); k>=64: C1=We@W1
__device__ __align__(8) float2 g_W2p[D_OUT * 32];
__device__ __align__(8) float2 g_c2p[32];         // (be@W1)[d], [d+32]
__device__ __align__(8) float2 g_b1p[32];
__device__ __align__(8) float2 g_b2p[32];
__device__ __align__(16) float g_scalef[D_OUT];
__device__ __align__(16) float g_shiftf[D_OUT];

// ---------------- kernel 0: zero accumulators ----------------
__global__ void zero_kernel() {
    int idx = blockIdx.x * blockDim.x + threadIdx.x;
    int stride = gridDim.x * blockDim.x;
    float4 z = make_float4(0.f, 0.f, 0.f, 0.f);
    for (int i = idx; i < N_NODES * (D_IN / 4); i += stride) ((float4*)g_aggX)[i] = z;
    for (int i = idx; i < N_NODES * (E_DIM / 4); i += stride) ((float4*)g_aggE)[i] = z;
    for (int i = idx; i < N_NODES; i += stride) g_deg[i] = 0.f;
    if (idx < D_OUT) { g_sum[idx] = 0.f; g_sumsq[idx] = 0.f; }
}

// ---------------- kernel 1: pack weights; C1 = We@W1; c2 = be@W1 --------------
__global__ void prep_kernel(const float* __restrict__ We,
                            const float* __restrict__ be,
                            const float* __restrict__ W1,
                            const float* __restrict__ b1,
                            const float* __restrict__ W2,
                            const float* __restrict__ b2) {
    __shared__ float W1s[D_IN * D_OUT];
    int tid = threadIdx.x;
    for (int i = tid; i < D_IN * D_OUT; i += 256) W1s[i] = W1[i];
    __syncthreads();
    for (int i = tid; i < 64 * 32; i += 256) {
        int k = i >> 5, l = i & 31;
        g_Wp[i] = make_float2(W1s[k * 64 + l], W1s[k * 64 + l + 32]);
    }
    for (int i = tid; i < E_DIM * 32; i += 256) {
        int kk = i >> 5, l = i & 31;
        float sa = 0.f, sb = 0.f;
        #pragma unroll 8
        for (int m = 0; m < 64; m++) {
            float w = We[kk * 64 + m];
            sa += w * W1s[m * 64 + l];
            sb += w * W1s[m * 64 + l + 32];
        }
        g_Wp[(64 + kk) * 32 + l] = make_float2(sa, sb);
    }
    for (int i = tid; i < 64 * 32; i += 256) {
        int k = i >> 5, l = i & 31;
        g_W2p[i] = make_float2(W2[k * 64 + l], W2[k * 64 + l + 32]);
    }
    if (tid < 32) {
        float sa = 0.f, sb = 0.f;
        #pragma unroll 8
        for (int m = 0; m < 64; m++) {
            float w = be[m];
            sa += w * W1s[m * 64 + tid];
            sb += w * W1s[m * 64 + tid + 32];
        }
        g_c2p[tid] = make_float2(sa, sb);
        g_b1p[tid] = make_float2(b1[tid], b1[tid + 32]);
        g_b2p[tid] = make_float2(b2[tid], b2[tid + 32]);
    }
}

// ---------------- kernel 2: edge scatter (vector float4 atomics; R3-proven) ---
__global__ void edge_kernel(const float4* __restrict__ x4,
                            const int* __restrict__ ei,
                            const float4* __restrict__ ea4) {
    int gwarp = (blockIdx.x * blockDim.x + threadIdx.x) >> 5;
    int lane = threadIdx.x & 31;
    int e0 = gwarp * 2;
    if (e0 >= N_EDGES) return;

    int half = lane >> 4, li = lane & 15;
    int e = e0 + half;
    bool v = (e < N_EDGES);
    int src = 0, dst = 0;
    if (v) {
        src = __ldg(&ei[e]);
        dst = __ldg(&ei[N_EDGES + e]);
    }
    if (v) {
        float4 xv = __ldg(&x4[(size_t)src * (D_IN / 4) + li]);
        atomicAdd(((float4*)(g_aggX + (size_t)dst * D_IN)) + li, xv);
    }
    int dA = __shfl_sync(0xffffffffu, dst, 0);
    int dB = __shfl_sync(0xffffffffu, dst, 16);
    if (lane < 16) {
        int e2 = e0 + (lane >> 3);
        if (e2 < N_EDGES) {
            int d2 = (lane < 8) ? dA : dB;
            int lj = lane & 7;
            float4 av = __ldg(&ea4[(size_t)e2 * (E_DIM / 4) + lj]);
            atomicAdd(((float4*)(g_aggE + (size_t)d2 * E_DIM)) + lj, av);
        }
    } else if (lane < 18) {
        int e3 = e0 + (lane - 16);
        if (e3 < N_EDGES) atomicAdd(&g_deg[(lane == 16) ? dA : dB], 1.f);
    }
}

// ---------------- kernel 3: node_h with f32x2 packed FMA ----------------------
// 8 warps/block, 4 rows/warp. Activations staged transposed: stT[k*4+r].
// Row quad read as 2 packed f32x2 (rows 01, rows 23). Lane owns dims d, d+32.
__global__ __launch_bounds__(256) void node_h_kernel(const float* __restrict__ x) {
    __shared__ __align__(8) float2 Wp[NK * 32];       // 24KB
    __shared__ __align__(16) float stT[8][NK * 4];    // 12KB
    __shared__ float2 c2s[32], b1s[32];
    __shared__ float bsum[64], bsq[64];

    int tid = threadIdx.x;
    for (int i = tid; i < NK * 32; i += 256) Wp[i] = g_Wp[i];
    if (tid < 32) { c2s[tid] = g_c2p[tid]; b1s[tid] = g_b1p[tid]; }
    if (tid < 64) { bsum[tid] = 0.f; bsq[tid] = 0.f; }
    __syncthreads();

    int warp = tid >> 5, lane = tid & 31;
    float2 c2v = c2s[lane], b1v = b1s[lane];
    float s0 = 0.f, q0 = 0.f, s1 = 0.f, q1 = 0.f;

    for (int g = blockIdx.x; g < NGROUPS; g += gridDim.x) {
        int rowBase = g * 32 + warp * 4;
        // stage 4 rows x 96 floats, transposed
        #pragma unroll
        for (int j = 0; j < 3; j++) {
            int task = j * 32 + lane;           // 0..95
            int r = task / 24, c = task % 24;   // c<16: x-part chunk, else aggE
            int row = rowBase + r;
            float4 v = make_float4(0.f, 0.f, 0.f, 0.f);
            if (row < N_NODES) {
                if (c < 16) {
                    float4 a = ((const float4*)g_aggX)[row * 16 + c];
                    float4 xv = __ldg(&((const float4*)x)[row * 16 + c]);
                    v = make_float4(a.x + xv.x, a.y + xv.y, a.z + xv.z, a.w + xv.w);
                } else {
                    v = ((const float4*)g_aggE)[row * 8 + (c - 16)];
                }
            }
            int k0 = c * 4;
            stT[warp][(k0 + 0) * 4 + r] = v.x;
            stT[warp][(k0 + 1) * 4 + r] = v.y;
            stT[warp][(k0 + 2) * 4 + r] = v.z;
            stT[warp][(k0 + 3) * 4 + r] = v.w;
        }
        __syncwarp();

        // init packed accumulators: acc01_a = (h_r0[d], h_r1[d]) etc.
        float dgv[4];
        #pragma unroll
        for (int r = 0; r < 4; r++) {
            int row = rowBase + r;
            dgv[r] = (row < N_NODES) ? g_deg[row] : 0.f;
        }
        unsigned long long acc01a, acc23a, acc01b, acc23b;
        {
            float h0 = dgv[0] * c2v.x + b1v.x, h1 = dgv[1] * c2v.x + b1v.x;
            float h2 = dgv[2] * c2v.x + b1v.x, h3 = dgv[3] * c2v.x + b1v.x;
            PACK2(acc01a, h0, h1); PACK2(acc23a, h2, h3);
            float g0 = dgv[0] * c2v.y + b1v.y, g1 = dgv[1] * c2v.y + b1v.y;
            float g2 = dgv[2] * c2v.y + b1v.y, g3 = dgv[3] * c2v.y + b1v.y;
            PACK2(acc01b, g0, g1); PACK2(acc23b, g2, g3);
        }
        const ulonglong2* st2 = (const ulonglong2*)&stT[warp][0];
        #pragma unroll 8
        for (int k = 0; k < NK; k++) {
            ulonglong2 av = st2[k];         // (a_r0,a_r1) , (a_r2,a_r3)
            float2 w = Wp[k * 32 + lane];
            unsigned long long wxx, wyy;
            PACK2(wxx, w.x, w.x);
            PACK2(wyy, w.y, w.y);
            FMA2(acc01a, av.x, wxx); FMA2(acc23a, av.y, wxx);
            FMA2(acc01b, av.x, wyy); FMA2(acc23b, av.y, wyy);
        }
        float h0[4], h1[4];
        UNPACK2(h0[0], h0[1], acc01a); UNPACK2(h0[2], h0[3], acc23a);
        UNPACK2(h1[0], h1[1], acc01b); UNPACK2(h1[2], h1[3], acc23b);
        #pragma unroll
        for (int r = 0; r < 4; r++) {
            int row = rowBase + r;
            if (row < N_NODES) {
                g_h[row * 64 + lane] = h0[r];
                g_h[row * 64 + 32 + lane] = h1[r];
                s0 += h0[r]; q0 += h0[r] * h0[r];
                s1 += h1[r]; q1 += h1[r] * h1[r];
            }
        }
        __syncwarp();
    }
    atomicAdd(&bsum[lane], s0);      atomicAdd(&bsq[lane], q0);
    atomicAdd(&bsum[lane + 32], s1); atomicAdd(&bsq[lane + 32], q1);
    __syncthreads();
    if (tid < 64) { atomicAdd(&g_sum[tid], bsum[tid]); atomicAdd(&g_sumsq[tid], bsq[tid]); }
}

// ---------------- kernel 4: bn finalize ----------------
__global__ void bn_kernel(const float* __restrict__ gamma,
                          const float* __restrict__ beta) {
    int d = threadIdx.x;   // 64 threads
    float n = (float)N_NODES;
    float mean = g_sum[d] / n;
    float var = g_sumsq[d] / n - mean * mean;
    float rstd = rsqrtf(var + BN_EPS);
    float sc = gamma[d] * rstd;
    g_scalef[d] = sc;
    g_shiftf[d] = beta[d] - mean * sc;
}

// ---------------- kernel 5: node_out with f32x2 packed FMA --------------------
__global__ __launch_bounds__(256) void node_out_kernel(float* __restrict__ out) {
    __shared__ __align__(8) float2 W2p[64 * 32];      // 16KB
    __shared__ __align__(16) float stT[8][64 * 4];    // 8KB
    __shared__ __align__(16) float scf[64], shf[64];
    __shared__ float2 b2s[32];

    int tid = threadIdx.x;
    for (int i = tid; i < 64 * 32; i += 256) W2p[i] = g_W2p[i];
    if (tid < 64) { scf[tid] = g_scalef[tid]; shf[tid] = g_shiftf[tid]; }
    if (tid < 32) b2s[tid] = g_b2p[tid];
    __syncthreads();

    int warp = tid >> 5, lane = tid & 31;
    float2 b2v = b2s[lane];

    for (int g = blockIdx.x; g < NGROUPS; g += gridDim.x) {
        int rowBase = g * 32 + warp * 4;
        #pragma unroll
        for (int j = 0; j < 2; j++) {
            int task = j * 32 + lane;          // 0..63
            int r = task >> 4, c = task & 15;
            int row = rowBase + r;
            float4 v = make_float4(0.f, 0.f, 0.f, 0.f);
            if (row < N_NODES) {
                float4 hv = ((const float4*)g_h)[row * 16 + c];
                float4 sc = ((const float4*)scf)[c];
                float4 sh = ((const float4*)shf)[c];
                v.x = fmaxf(0.f, hv.x * sc.x + sh.x);
                v.y = fmaxf(0.f, hv.y * sc.y + sh.y);
                v.z = fmaxf(0.f, hv.z * sc.z + sh.z);
                v.w = fmaxf(0.f, hv.w * sc.w + sh.w);
            }
            int k0 = c * 4;
            stT[warp][(k0 + 0) * 4 + r] = v.x;
            stT[warp][(k0 + 1) * 4 + r] = v.y;
            stT[warp][(k0 + 2) * 4 + r] = v.z;
            stT[warp][(k0 + 3) * 4 + r] = v.w;
        }
        __syncwarp();

        unsigned long long acc01a, acc23a, acc01b, acc23b;
        PACK2(acc01a, b2v.x, b2v.x); acc23a = acc01a;
        PACK2(acc01b, b2v.y, b2v.y); acc23b = acc01b;
        const ulonglong2* st2 = (const ulonglong2*)&stT[warp][0];
        #pragma unroll 8
        for (int k = 0; k < 64; k++) {
            ulonglong2 av = st2[k];
            float2 w = W2p[k * 32 + lane];
            unsigned long long wxx, wyy;
            PACK2(wxx, w.x, w.x);
            PACK2(wyy, w.y, w.y);
            FMA2(acc01a, av.x, wxx); FMA2(acc23a, av.y, wxx);
            FMA2(acc01b, av.x, wyy); FMA2(acc23b, av.y, wyy);
        }
        float y0[4], y1[4];
        UNPACK2(y0[0], y0[1], acc01a); UNPACK2(y0[2], y0[3], acc23a);
        UNPACK2(y1[0], y1[1], acc01b); UNPACK2(y1[2], y1[3], acc23b);
        #pragma unroll
        for (int r = 0; r < 4; r++) {
            int row = rowBase + r;
            if (row < N_NODES) {
                out[row * 64 + lane] = y0[r];
                out[row * 64 + 32 + lane] = y1[r];
            }
        }
        __syncwarp();
    }
}

// ---------------- launch ----------------
extern "C" void kernel_launch(void* const* d_in, const int* in_sizes, int n_in,
                              void* d_out, int out_size) {
    const float* x     = (const float*)d_in[0];
    const int* ei      = (const int*)d_in[1];
    const float* ea    = (const float*)d_in[2];
    const float* We    = (const float*)d_in[3];
    const float* be    = (const float*)d_in[4];
    const float* W1    = (const float*)d_in[5];
    const float* b1    = (const float*)d_in[6];
    const float* gamma = (const float*)d_in[7];
    const float* beta  = (const float*)d_in[8];
    const float* W2    = (const float*)d_in[9];
    const float* b2    = (const float*)d_in[10];
    float* out         = (float*)d_out;

    zero_kernel<<<2048, 256>>>();
    prep_kernel<<<1, 256>>>(We, be, W1, b1, W2, b2);

    int nWarps = (N_EDGES + 1) / 2;
    int nBlocks = (nWarps + 7) / 8;
    edge_kernel<<<nBlocks, 256>>>((const float4*)x, ei, (const float4*)ea);

    node_h_kernel<<<NGROUPS, 256>>>(x);
    bn_kernel<<<1, 64>>>(gamma, beta);
    node_out_kernel<<<NGROUPS, 256>>>(out);
}